// round 1
// baseline (speedup 1.0000x reference)
#include <cuda_runtime.h>

#define NUSER 150000
#define NITEM 75000
#define NTOT  225000
#define DD    64
#define NNZV  2000000
#define VSCALE 0.01f

// ---------------- static device scratch (no allocations allowed) ----------------
__device__ int   g_cnt[NTOT];
__device__ int   g_inc[NTOT];
__device__ int   g_bsum[256];
__device__ int   g_boff[256];
__device__ int   g_rowptr[NTOT + 1];
__device__ int   g_wptr[NTOT + 1];
__device__ int   g_col[NNZV];
__device__ float g_val[NNZV];
__device__ float g_bufA[(size_t)NTOT * DD];
__device__ float g_bufB[(size_t)NTOT * DD];
__device__ float g_accbuf[(size_t)NTOT * DD];

// ---------------- sort: COO -> CSR ----------------
__global__ void k_zero_cnt() {
    int i = blockIdx.x * blockDim.x + threadIdx.x;
    if (i < NTOT) g_cnt[i] = 0;
}

__global__ void k_hist(const int* __restrict__ rows) {
    int e = blockIdx.x * blockDim.x + threadIdx.x;
    if (e < NNZV) atomicAdd(&g_cnt[rows[e]], 1);
}

// block-wide inclusive scan over 1024-element chunks
__global__ void k_scan1() {
    __shared__ int s[1024];
    int tid = threadIdx.x;
    int i = blockIdx.x * 1024 + tid;
    int v = (i < NTOT) ? g_cnt[i] : 0;
    s[tid] = v;
    __syncthreads();
    for (int off = 1; off < 1024; off <<= 1) {
        int t = 0;
        if (tid >= off) t = s[tid - off];
        __syncthreads();
        s[tid] += t;
        __syncthreads();
    }
    if (i < NTOT) g_inc[i] = s[tid];
    if (tid == 1023) g_bsum[blockIdx.x] = s[1023];
}

// single-block scan of (<=256) block sums -> exclusive offsets
__global__ void k_scan2(int nblocks) {
    __shared__ int s[256];
    int tid = threadIdx.x;
    int v = (tid < nblocks) ? g_bsum[tid] : 0;
    s[tid] = v;
    __syncthreads();
    for (int off = 1; off < 256; off <<= 1) {
        int t = 0;
        if (tid >= off) t = s[tid - off];
        __syncthreads();
        s[tid] += t;
        __syncthreads();
    }
    g_boff[tid] = s[tid] - v;   // exclusive
}

__global__ void k_scan3() {
    int i = blockIdx.x * blockDim.x + threadIdx.x;
    if (i < NTOT) {
        int val = g_inc[i] + g_boff[i >> 10];
        g_rowptr[i + 1] = val;
        g_wptr[i + 1] = val;
        if (i == 0) { g_rowptr[0] = 0; g_wptr[0] = 0; }
    }
}

__global__ void k_scatter(const int* __restrict__ rows,
                          const int* __restrict__ cols,
                          const float* __restrict__ vals) {
    int e = blockIdx.x * blockDim.x + threadIdx.x;
    if (e < NNZV) {
        int r = rows[e];
        int p = atomicAdd(&g_wptr[r], 1);
        g_col[p] = cols[e];
        g_val[p] = vals[e];
    }
}

// ---------------- SpMM: warp per row ----------------
// MODE 0: acc = sum   MODE 1: acc += sum
template <int MODE>
__global__ void k_spmm(const float* __restrict__ xa,
                       const float* __restrict__ xb,
                       int split,
                       float* __restrict__ y,
                       float* __restrict__ acc,
                       int write_y) {
    int warp = threadIdx.x >> 5;
    int lane = threadIdx.x & 31;
    int row = blockIdx.x * 8 + warp;   // NTOT divisible by 8
    int start = g_rowptr[row];
    int end = g_rowptr[row + 1];

    float a0 = 0.f, a1 = 0.f;
    for (int base = start; base < end; base += 32) {
        int e = base + lane;
        int c = 0;
        float v = 0.f;
        if (e < end) { c = g_col[e]; v = g_val[e]; }
        int cnt = min(32, end - base);
        for (int k = 0; k < cnt; k++) {
            int   cc = __shfl_sync(0xffffffffu, c, k);
            float vv = __shfl_sync(0xffffffffu, v, k);
            const float* xr = (cc < split) ? (xa + (size_t)cc * DD)
                                           : (xb + (size_t)(cc - split) * DD);
            a0 += vv * __ldg(xr + lane);
            a1 += vv * __ldg(xr + lane + 32);
        }
    }
    int o = row * DD + lane;
    if (write_y) { y[o] = a0; y[o + 32] = a1; }
    if (MODE == 0) { acc[o] = a0; acc[o + 32] = a1; }
    else           { acc[o] += a0; acc[o + 32] += a1; }
}

// ---------------- epilogue: mean, GEMM 64x64, exp, views ----------------
// warp handles 8 rows (amortizes shared W reads); block = 8 warps = 64 rows
__global__ void k_epilogue(const float* __restrict__ acc,
                           const float* __restrict__ W,
                           const float* __restrict__ bias,
                           const float* __restrict__ n1,
                           const float* __restrict__ n2,
                           float* __restrict__ out_mean,
                           float* __restrict__ out_std,
                           float* __restrict__ out_v1,
                           float* __restrict__ out_v2) {
    __shared__ float2 Ws[64 * 32];   // Ws[d*32+l] = {W[d][l], W[d][l+32]}
    for (int i = threadIdx.x; i < 64 * 32; i += blockDim.x) {
        int d = i >> 5, l = i & 31;
        Ws[i] = make_float2(W[d * 64 + l], W[d * 64 + 32 + l]);
    }
    __syncthreads();

    int lane = threadIdx.x & 31;
    int warp = threadIdx.x >> 5;
    int rowbase = blockIdx.x * 64 + warp * 8;

    float b0 = __ldg(bias + lane);
    float b1 = __ldg(bias + lane + 32);

    float m0[8], m1[8], ls0[8], ls1[8];
#pragma unroll
    for (int r = 0; r < 8; r++) {
        int row = rowbase + r;
        if (row >= NTOT) row = NTOT - 1;
        m0[r] = acc[(size_t)row * DD + lane] * (1.f / 3.f);
        m1[r] = acc[(size_t)row * DD + lane + 32] * (1.f / 3.f);
        ls0[r] = b0;
        ls1[r] = b1;
    }

#pragma unroll 4
    for (int d = 0; d < 32; d++) {
        float2 w = Ws[d * 32 + lane];
#pragma unroll
        for (int r = 0; r < 8; r++) {
            float md = __shfl_sync(0xffffffffu, m0[r], d);
            ls0[r] += md * w.x;
            ls1[r] += md * w.y;
        }
    }
#pragma unroll 4
    for (int d = 0; d < 32; d++) {
        float2 w = Ws[(d + 32) * 32 + lane];
#pragma unroll
        for (int r = 0; r < 8; r++) {
            float md = __shfl_sync(0xffffffffu, m1[r], d);
            ls0[r] += md * w.x;
            ls1[r] += md * w.y;
        }
    }

#pragma unroll
    for (int r = 0; r < 8; r++) {
        int row = rowbase + r;
        if (row < NTOT) {
            float s0 = __expf(ls0[r]);
            float s1 = __expf(ls1[r]);
            size_t i0 = (size_t)row * DD + lane;
            size_t i1 = i0 + 32;
            float na = __ldg(n1 + i0), nb = __ldg(n1 + i1);
            float nc = __ldg(n2 + i0), nd = __ldg(n2 + i1);
            out_mean[i0] = m0[r];  out_mean[i1] = m1[r];
            out_std[i0] = s0;      out_std[i1] = s1;
            out_v1[i0] = m0[r] + s0 * na * VSCALE;
            out_v1[i1] = m1[r] + s1 * nb * VSCALE;
            out_v2[i0] = m0[r] + s0 * nc * VSCALE;
            out_v2[i1] = m1[r] + s1 * nd * VSCALE;
        }
    }
}

// ---------------- launch ----------------
extern "C" void kernel_launch(void* const* d_in, const int* in_sizes, int n_in,
                              void* d_out, int out_size) {
    const float* user = (const float*)d_in[0];
    const float* item = (const float*)d_in[1];
    const float* W    = (const float*)d_in[2];
    const float* bias = (const float*)d_in[3];
    const int*   rows = (const int*)d_in[4];
    const int*   cols = (const int*)d_in[5];
    const float* vals = (const float*)d_in[6];
    const float* n1   = (const float*)d_in[7];
    const float* n2   = (const float*)d_in[8];
    // d_in[9] = gcn_layer (constant 3, hardcoded)

    float *bufA, *bufB, *acc;
    cudaGetSymbolAddress((void**)&bufA, g_bufA);
    cudaGetSymbolAddress((void**)&bufB, g_bufB);
    cudaGetSymbolAddress((void**)&acc, g_accbuf);

    float* out_mean = (float*)d_out;
    float* out_std  = out_mean + (size_t)NTOT * DD;
    float* out_v1   = out_std + (size_t)NTOT * DD;
    float* out_v2   = out_v1 + (size_t)NTOT * DD;

    const int T = 256;
    int nbN = (NTOT + T - 1) / T;       // 879
    int nbE = (NNZV + T - 1) / T;       // 7813
    int nbScan = (NTOT + 1023) / 1024;  // 220

    // sort COO -> CSR
    k_zero_cnt<<<nbN, T>>>();
    k_hist<<<nbE, T>>>(rows);
    k_scan1<<<nbScan, 1024>>>();
    k_scan2<<<1, 256>>>(nbScan);
    k_scan3<<<nbN, T>>>();
    k_scatter<<<nbE, T>>>(rows, cols, vals);

    // 3 GCN layers, acc = y1 + y2 + y3
    int nbSpmm = NTOT / 8;              // 28125
    k_spmm<0><<<nbSpmm, T>>>(user, item, NUSER, bufA, acc, 1);   // L1: acc = y1
    k_spmm<1><<<nbSpmm, T>>>(bufA, bufA, NTOT, bufB, acc, 1);    // L2: acc += y2
    k_spmm<1><<<nbSpmm, T>>>(bufB, bufB, NTOT, bufA, acc, 0);    // L3: acc += y3 (y unused)

    // epilogue
    int nbEpi = (NTOT + 63) / 64;       // 3516
    k_epilogue<<<nbEpi, T>>>(acc, W, bias, n1, n2, out_mean, out_std, out_v1, out_v2);
}

// round 2
// speedup vs baseline: 1.1284x; 1.1284x over previous
#include <cuda_runtime.h>

#define NUSER 150000
#define NITEM 75000
#define NTOT  225000
#define DD    64
#define NNZV  2000000
#define VSCALE 0.01f

// ---------------- static device scratch (no allocations allowed) ----------------
__device__ int   g_cnt[NTOT];
__device__ int   g_inc[NTOT];
__device__ int   g_bsum[256];
__device__ int   g_boff[256];
__device__ int   g_rowptr[NTOT + 1];
__device__ int   g_wptr[NTOT + 1];
__device__ int2  g_edge[NNZV];          // {col, val-as-int}
__device__ float g_bufA[(size_t)NTOT * DD];
__device__ float g_bufB[(size_t)NTOT * DD];
__device__ float g_bufC[(size_t)NTOT * DD];

// ---------------- sort: COO -> CSR ----------------
__global__ void k_zero_cnt() {
    int i = blockIdx.x * blockDim.x + threadIdx.x;
    if (i < NTOT) g_cnt[i] = 0;
}

__global__ void k_hist(const int* __restrict__ rows) {
    int e = blockIdx.x * blockDim.x + threadIdx.x;
    if (e < NNZV) atomicAdd(&g_cnt[rows[e]], 1);
}

__global__ void k_scan1() {
    __shared__ int s[1024];
    int tid = threadIdx.x;
    int i = blockIdx.x * 1024 + tid;
    int v = (i < NTOT) ? g_cnt[i] : 0;
    s[tid] = v;
    __syncthreads();
    for (int off = 1; off < 1024; off <<= 1) {
        int t = 0;
        if (tid >= off) t = s[tid - off];
        __syncthreads();
        s[tid] += t;
        __syncthreads();
    }
    if (i < NTOT) g_inc[i] = s[tid];
    if (tid == 1023) g_bsum[blockIdx.x] = s[1023];
}

__global__ void k_scan2(int nblocks) {
    __shared__ int s[256];
    int tid = threadIdx.x;
    int v = (tid < nblocks) ? g_bsum[tid] : 0;
    s[tid] = v;
    __syncthreads();
    for (int off = 1; off < 256; off <<= 1) {
        int t = 0;
        if (tid >= off) t = s[tid - off];
        __syncthreads();
        s[tid] += t;
        __syncthreads();
    }
    g_boff[tid] = s[tid] - v;   // exclusive
}

__global__ void k_scan3() {
    int i = blockIdx.x * blockDim.x + threadIdx.x;
    if (i < NTOT) {
        int val = g_inc[i] + g_boff[i >> 10];
        g_rowptr[i + 1] = val;
        g_wptr[i + 1] = val;
        if (i == 0) { g_rowptr[0] = 0; g_wptr[0] = 0; }
    }
}

__global__ void k_scatter(const int* __restrict__ rows,
                          const int* __restrict__ cols,
                          const float* __restrict__ vals) {
    int e = blockIdx.x * blockDim.x + threadIdx.x;
    if (e < NNZV) {
        int r = rows[e];
        int p = atomicAdd(&g_wptr[r], 1);
        g_edge[p] = make_int2(cols[e], __float_as_int(vals[e]));
    }
}

// ---------------- SpMM: warp per row, float2 lanes, smem edge broadcast --------
__global__ void k_spmm(const float2* __restrict__ xa,
                       const float2* __restrict__ xb,
                       int split,
                       float2* __restrict__ y) {
    __shared__ long long sedge[8 * 32];
    int warp = threadIdx.x >> 5;
    int lane = threadIdx.x & 31;
    long long* se = sedge + warp * 32;
    int row = blockIdx.x * 8 + warp;   // NTOT divisible by 8
    int start = g_rowptr[row];
    int end = g_rowptr[row + 1];

    float2 a = make_float2(0.f, 0.f);
    for (int base = start; base < end; base += 32) {
        int e = base + lane;
        if (e < end)
            se[lane] = *reinterpret_cast<const long long*>(&g_edge[e]);
        __syncwarp();
        int cnt = min(32, end - base);
        for (int k = 0; k < cnt; k++) {
            long long q = se[k];
            int   cc = (int)(unsigned int)(q & 0xffffffffll);
            float vv = __int_as_float((int)(q >> 32));
            const float2* xr = (cc < split) ? (xa + (size_t)cc * 32)
                                            : (xb + (size_t)(cc - split) * 32);
            float2 xv = __ldg(xr + lane);
            a.x += vv * xv.x;
            a.y += vv * xv.y;
        }
        __syncwarp();
    }
    y[(size_t)row * 32 + lane] = a;
}

// ---------------- epilogue: mean of 3 bufs, GEMM 64x64, exp, views ----------------
__global__ void k_epilogue(const float* __restrict__ A,
                           const float* __restrict__ B,
                           const float* __restrict__ C,
                           const float* __restrict__ W,
                           const float* __restrict__ bias,
                           const float* __restrict__ n1,
                           const float* __restrict__ n2,
                           float* __restrict__ out_mean,
                           float* __restrict__ out_std,
                           float* __restrict__ out_v1,
                           float* __restrict__ out_v2) {
    __shared__ float2 Ws[64 * 32];   // Ws[d*32+l] = {W[d][l], W[d][l+32]}
    for (int i = threadIdx.x; i < 64 * 32; i += blockDim.x) {
        int d = i >> 5, l = i & 31;
        Ws[i] = make_float2(W[d * 64 + l], W[d * 64 + 32 + l]);
    }
    __syncthreads();

    int lane = threadIdx.x & 31;
    int warp = threadIdx.x >> 5;
    int rowbase = blockIdx.x * 64 + warp * 8;

    float b0 = __ldg(bias + lane);
    float b1 = __ldg(bias + lane + 32);

    float m0[8], m1[8], ls0[8], ls1[8];
#pragma unroll
    for (int r = 0; r < 8; r++) {
        int row = rowbase + r;
        if (row >= NTOT) row = NTOT - 1;
        size_t i0 = (size_t)row * DD + lane;
        size_t i1 = i0 + 32;
        m0[r] = (__ldg(A + i0) + __ldg(B + i0) + __ldg(C + i0)) * (1.f / 3.f);
        m1[r] = (__ldg(A + i1) + __ldg(B + i1) + __ldg(C + i1)) * (1.f / 3.f);
        ls0[r] = b0;
        ls1[r] = b1;
    }

#pragma unroll 4
    for (int d = 0; d < 32; d++) {
        float2 w = Ws[d * 32 + lane];
#pragma unroll
        for (int r = 0; r < 8; r++) {
            float md = __shfl_sync(0xffffffffu, m0[r], d);
            ls0[r] += md * w.x;
            ls1[r] += md * w.y;
        }
    }
#pragma unroll 4
    for (int d = 0; d < 32; d++) {
        float2 w = Ws[(d + 32) * 32 + lane];
#pragma unroll
        for (int r = 0; r < 8; r++) {
            float md = __shfl_sync(0xffffffffu, m1[r], d);
            ls0[r] += md * w.x;
            ls1[r] += md * w.y;
        }
    }

#pragma unroll
    for (int r = 0; r < 8; r++) {
        int row = rowbase + r;
        if (row < NTOT) {
            float s0 = __expf(ls0[r]);
            float s1 = __expf(ls1[r]);
            size_t i0 = (size_t)row * DD + lane;
            size_t i1 = i0 + 32;
            float na = __ldg(n1 + i0), nb = __ldg(n1 + i1);
            float nc = __ldg(n2 + i0), nd = __ldg(n2 + i1);
            out_mean[i0] = m0[r];  out_mean[i1] = m1[r];
            out_std[i0] = s0;      out_std[i1] = s1;
            out_v1[i0] = m0[r] + s0 * na * VSCALE;
            out_v1[i1] = m1[r] + s1 * nb * VSCALE;
            out_v2[i0] = m0[r] + s0 * nc * VSCALE;
            out_v2[i1] = m1[r] + s1 * nd * VSCALE;
        }
    }
}

// ---------------- launch ----------------
extern "C" void kernel_launch(void* const* d_in, const int* in_sizes, int n_in,
                              void* d_out, int out_size) {
    const float* user = (const float*)d_in[0];
    const float* item = (const float*)d_in[1];
    const float* W    = (const float*)d_in[2];
    const float* bias = (const float*)d_in[3];
    const int*   rows = (const int*)d_in[4];
    const int*   cols = (const int*)d_in[5];
    const float* vals = (const float*)d_in[6];
    const float* n1   = (const float*)d_in[7];
    const float* n2   = (const float*)d_in[8];

    float *bufA, *bufB, *bufC;
    cudaGetSymbolAddress((void**)&bufA, g_bufA);
    cudaGetSymbolAddress((void**)&bufB, g_bufB);
    cudaGetSymbolAddress((void**)&bufC, g_bufC);

    float* out_mean = (float*)d_out;
    float* out_std  = out_mean + (size_t)NTOT * DD;
    float* out_v1   = out_std + (size_t)NTOT * DD;
    float* out_v2   = out_v1 + (size_t)NTOT * DD;

    const int T = 256;
    int nbN = (NTOT + T - 1) / T;
    int nbE = (NNZV + T - 1) / T;
    int nbScan = (NTOT + 1023) / 1024;

    // sort COO -> CSR
    k_zero_cnt<<<nbN, T>>>();
    k_hist<<<nbE, T>>>(rows);
    k_scan1<<<nbScan, 1024>>>();
    k_scan2<<<1, 256>>>(nbScan);
    k_scan3<<<nbN, T>>>();
    k_scatter<<<nbE, T>>>(rows, cols, vals);

    // 3 GCN layers, each writes only its own buffer
    int nbSpmm = NTOT / 8;
    k_spmm<<<nbSpmm, T>>>((const float2*)user, (const float2*)item, NUSER,
                          (float2*)bufA);                               // y1
    k_spmm<<<nbSpmm, T>>>((const float2*)bufA, (const float2*)bufA, NTOT,
                          (float2*)bufB);                               // y2
    k_spmm<<<nbSpmm, T>>>((const float2*)bufB, (const float2*)bufB, NTOT,
                          (float2*)bufC);                               // y3

    // epilogue: mean = (A+B+C)/3, logstd GEMM, exp, views
    int nbEpi = (NTOT + 63) / 64;
    k_epilogue<<<nbEpi, T>>>(bufA, bufB, bufC, W, bias, n1, n2,
                             out_mean, out_std, out_v1, out_v2);
}

// round 3
// speedup vs baseline: 1.2565x; 1.1135x over previous
#include <cuda_runtime.h>
#include <cuda_fp16.h>

#define NUSER 150000
#define NITEM 75000
#define NTOT  225000
#define DD    64
#define NNZV  2000000
#define VSCALE 0.01f

// ---------------- static device scratch ----------------
__device__ int   g_cnt[NTOT];
__device__ int   g_inc[NTOT];
__device__ int   g_bsum[256];
__device__ int   g_boff[256];
__device__ int   g_rowptr[NTOT + 1];
__device__ int   g_wptr[NTOT + 1];
__device__ int2  g_edge[NNZV];                    // {col, val-as-int}
__device__ __half2 g_x0[(size_t)NTOT * 32];       // fused user+item, fp16
__device__ __half2 g_h1[(size_t)NTOT * 32];
__device__ __half2 g_h2[(size_t)NTOT * 32];
__device__ __half2 g_h3[(size_t)NTOT * 32];

// ---------------- sort: COO -> CSR ----------------
__global__ void k_zero_cnt() {
    int i = blockIdx.x * blockDim.x + threadIdx.x;
    if (i < NTOT) g_cnt[i] = 0;
}

__global__ void k_hist(const int* __restrict__ rows) {
    int e = blockIdx.x * blockDim.x + threadIdx.x;
    if (e < NNZV) atomicAdd(&g_cnt[rows[e]], 1);
}

__global__ void k_scan1() {
    __shared__ int s[1024];
    int tid = threadIdx.x;
    int i = blockIdx.x * 1024 + tid;
    int v = (i < NTOT) ? g_cnt[i] : 0;
    s[tid] = v;
    __syncthreads();
    for (int off = 1; off < 1024; off <<= 1) {
        int t = 0;
        if (tid >= off) t = s[tid - off];
        __syncthreads();
        s[tid] += t;
        __syncthreads();
    }
    if (i < NTOT) g_inc[i] = s[tid];
    if (tid == 1023) g_bsum[blockIdx.x] = s[1023];
}

__global__ void k_scan2(int nblocks) {
    __shared__ int s[256];
    int tid = threadIdx.x;
    int v = (tid < nblocks) ? g_bsum[tid] : 0;
    s[tid] = v;
    __syncthreads();
    for (int off = 1; off < 256; off <<= 1) {
        int t = 0;
        if (tid >= off) t = s[tid - off];
        __syncthreads();
        s[tid] += t;
        __syncthreads();
    }
    g_boff[tid] = s[tid] - v;   // exclusive
}

__global__ void k_scan3() {
    int i = blockIdx.x * blockDim.x + threadIdx.x;
    if (i < NTOT) {
        int val = g_inc[i] + g_boff[i >> 10];
        g_rowptr[i + 1] = val;
        g_wptr[i + 1] = val;
        if (i == 0) { g_rowptr[0] = 0; g_wptr[0] = 0; }
    }
}

__global__ void k_scatter(const int* __restrict__ rows,
                          const int* __restrict__ cols,
                          const float* __restrict__ vals) {
    int e = blockIdx.x * blockDim.x + threadIdx.x;
    if (e < NNZV) {
        int r = rows[e];
        int p = atomicAdd(&g_wptr[r], 1);
        g_edge[p] = make_int2(cols[e], __float_as_int(vals[e]));
    }
}

// ---------------- convert user+item fp32 -> fused fp16 buffer ----------------
__global__ void k_convert(const float2* __restrict__ user,
                          const float2* __restrict__ item) {
    int i = blockIdx.x * blockDim.x + threadIdx.x;   // over NTOT*32 float2-pairs
    if (i < NTOT * 32) {
        float2 v = (i < NUSER * 32) ? __ldg(user + i)
                                    : __ldg(item + (i - NUSER * 32));
        g_x0[i] = __floats2half2_rn(v.x, v.y);
    }
}

// ---------------- SpMM: warp per row, half2 lanes, smem edge broadcast --------
__global__ void k_spmm(const __half2* __restrict__ x,
                       __half2* __restrict__ y) {
    __shared__ long long sedge[8 * 32];
    int warp = threadIdx.x >> 5;
    int lane = threadIdx.x & 31;
    long long* se = sedge + warp * 32;
    int row = blockIdx.x * 8 + warp;   // NTOT divisible by 8
    int start = g_rowptr[row];
    int end = g_rowptr[row + 1];

    float ax = 0.f, ay = 0.f;
    for (int base = start; base < end; base += 32) {
        int e = base + lane;
        if (e < end)
            se[lane] = *reinterpret_cast<const long long*>(&g_edge[e]);
        __syncwarp();
        int cnt = min(32, end - base);
#pragma unroll 4
        for (int k = 0; k < cnt; k++) {
            long long q = se[k];
            int   cc = (int)(unsigned int)(q & 0xffffffffll);
            float vv = __int_as_float((int)(q >> 32));
            __half2 h = __ldg(x + (size_t)cc * 32 + lane);
            float2 xv = __half22float2(h);
            ax += vv * xv.x;
            ay += vv * xv.y;
        }
        __syncwarp();
    }
    y[(size_t)row * 32 + lane] = __floats2half2_rn(ax, ay);
}

// ---------------- epilogue: mean of 3 half bufs, GEMM 64x64, exp, views -------
// pair-per-lane layout: lane owns elements (2*lane, 2*lane+1)
__global__ void k_epilogue(const __half2* __restrict__ A,
                           const __half2* __restrict__ B,
                           const __half2* __restrict__ C,
                           const float* __restrict__ W,
                           const float* __restrict__ bias,
                           const float2* __restrict__ n1,
                           const float2* __restrict__ n2,
                           float2* __restrict__ out_mean,
                           float2* __restrict__ out_std,
                           float2* __restrict__ out_v1,
                           float2* __restrict__ out_v2) {
    __shared__ float2 Ws[64 * 32];   // Ws[d*32+l] = {W[d][2l], W[d][2l+1]}
    for (int i = threadIdx.x; i < 64 * 32; i += blockDim.x) {
        int d = i >> 5, l = i & 31;
        Ws[i] = *reinterpret_cast<const float2*>(W + d * 64 + 2 * l);
    }
    __syncthreads();

    int lane = threadIdx.x & 31;
    int warp = threadIdx.x >> 5;
    int rowbase = blockIdx.x * 64 + warp * 8;

    float2 b = __ldg(reinterpret_cast<const float2*>(bias) + lane);

    float m0[8], m1[8], ls0[8], ls1[8];
#pragma unroll
    for (int r = 0; r < 8; r++) {
        int row = rowbase + r;
        if (row >= NTOT) row = NTOT - 1;
        size_t ix = (size_t)row * 32 + lane;
        float2 a = __half22float2(__ldg(A + ix));
        float2 bb = __half22float2(__ldg(B + ix));
        float2 c = __half22float2(__ldg(C + ix));
        m0[r] = (a.x + bb.x + c.x) * (1.f / 3.f);
        m1[r] = (a.y + bb.y + c.y) * (1.f / 3.f);
        ls0[r] = b.x;
        ls1[r] = b.y;
    }

#pragma unroll 4
    for (int dd = 0; dd < 32; dd++) {
        float2 w0 = Ws[(2 * dd) * 32 + lane];       // W row 2dd
        float2 w1 = Ws[(2 * dd + 1) * 32 + lane];   // W row 2dd+1
#pragma unroll
        for (int r = 0; r < 8; r++) {
            float md0 = __shfl_sync(0xffffffffu, m0[r], dd);  // mean[2dd]
            float md1 = __shfl_sync(0xffffffffu, m1[r], dd);  // mean[2dd+1]
            ls0[r] += md0 * w0.x + md1 * w1.x;
            ls1[r] += md0 * w0.y + md1 * w1.y;
        }
    }

#pragma unroll
    for (int r = 0; r < 8; r++) {
        int row = rowbase + r;
        if (row < NTOT) {
            float s0 = __expf(ls0[r]);
            float s1 = __expf(ls1[r]);
            size_t ix = (size_t)row * 32 + lane;
            float2 na = __ldg(n1 + ix);
            float2 nc = __ldg(n2 + ix);
            out_mean[ix] = make_float2(m0[r], m1[r]);
            out_std[ix]  = make_float2(s0, s1);
            out_v1[ix] = make_float2(m0[r] + s0 * na.x * VSCALE,
                                     m1[r] + s1 * na.y * VSCALE);
            out_v2[ix] = make_float2(m0[r] + s0 * nc.x * VSCALE,
                                     m1[r] + s1 * nc.y * VSCALE);
        }
    }
}

// ---------------- launch ----------------
extern "C" void kernel_launch(void* const* d_in, const int* in_sizes, int n_in,
                              void* d_out, int out_size) {
    const float* user = (const float*)d_in[0];
    const float* item = (const float*)d_in[1];
    const float* W    = (const float*)d_in[2];
    const float* bias = (const float*)d_in[3];
    const int*   rows = (const int*)d_in[4];
    const int*   cols = (const int*)d_in[5];
    const float* vals = (const float*)d_in[6];
    const float* n1   = (const float*)d_in[7];
    const float* n2   = (const float*)d_in[8];

    __half2 *x0, *h1, *h2, *h3;
    cudaGetSymbolAddress((void**)&x0, g_x0);
    cudaGetSymbolAddress((void**)&h1, g_h1);
    cudaGetSymbolAddress((void**)&h2, g_h2);
    cudaGetSymbolAddress((void**)&h3, g_h3);

    float* out = (float*)d_out;
    float2* out_mean = (float2*)out;
    float2* out_std  = (float2*)(out + (size_t)NTOT * DD);
    float2* out_v1   = (float2*)(out + 2 * (size_t)NTOT * DD);
    float2* out_v2   = (float2*)(out + 3 * (size_t)NTOT * DD);

    const int T = 256;
    int nbN = (NTOT + T - 1) / T;
    int nbE = (NNZV + T - 1) / T;
    int nbScan = (NTOT + 1023) / 1024;
    int nbCvt = (NTOT * 32 + T - 1) / T;

    // sort COO -> CSR
    k_zero_cnt<<<nbN, T>>>();
    k_hist<<<nbE, T>>>(rows);
    k_scan1<<<nbScan, 1024>>>();
    k_scan2<<<1, 256>>>(nbScan);
    k_scan3<<<nbN, T>>>();
    k_scatter<<<nbE, T>>>(rows, cols, vals);

    // fp32 -> fp16 fused input
    k_convert<<<nbCvt, T>>>((const float2*)user, (const float2*)item);

    // 3 GCN layers, each writes its own half buffer
    int nbSpmm = NTOT / 8;
    k_spmm<<<nbSpmm, T>>>(x0, h1);
    k_spmm<<<nbSpmm, T>>>(h1, h2);
    k_spmm<<<nbSpmm, T>>>(h2, h3);

    // epilogue: mean = (h1+h2+h3)/3, logstd GEMM, exp, views
    int nbEpi = (NTOT + 63) / 64;
    k_epilogue<<<nbEpi, T>>>(h1, h2, h3, W, bias,
                             (const float2*)n1, (const float2*)n2,
                             out_mean, out_std, out_v1, out_v2);
}

// round 4
// speedup vs baseline: 1.3013x; 1.0357x over previous
#include <cuda_runtime.h>
#include <cuda_fp16.h>

#define NUSER 150000
#define NITEM 75000
#define NTOT  225000
#define DD    64
#define NNZV  2000000
#define VSCALE 0.01f

// ---------------- static device scratch ----------------
__device__ int   g_cnt[NTOT];
__device__ int   g_inc[NTOT];
__device__ int   g_bsum[256];
__device__ int   g_boff[256];
__device__ int   g_rowptr[NTOT + 1];
__device__ int   g_wptr[NTOT + 1];
__device__ int2  g_edge[NNZV];                    // {col, val-as-int}
__device__ __half2 g_x0[(size_t)NTOT * 32];       // fused user+item, fp16
__device__ __half2 g_h1[(size_t)NTOT * 32];
__device__ __half2 g_h2[(size_t)NTOT * 32];
__device__ __half2 g_h3[(size_t)NTOT * 32];

// ---------------- sort: COO -> CSR ----------------
__global__ void k_zero_cnt() {
    int i = blockIdx.x * blockDim.x + threadIdx.x;
    if (i < NTOT) g_cnt[i] = 0;
}

__global__ void k_hist(const int* __restrict__ rows) {
    int e = blockIdx.x * blockDim.x + threadIdx.x;
    if (e < NNZV) atomicAdd(&g_cnt[rows[e]], 1);
}

__global__ void k_scan1() {
    __shared__ int s[1024];
    int tid = threadIdx.x;
    int i = blockIdx.x * 1024 + tid;
    int v = (i < NTOT) ? g_cnt[i] : 0;
    s[tid] = v;
    __syncthreads();
    for (int off = 1; off < 1024; off <<= 1) {
        int t = 0;
        if (tid >= off) t = s[tid - off];
        __syncthreads();
        s[tid] += t;
        __syncthreads();
    }
    if (i < NTOT) g_inc[i] = s[tid];
    if (tid == 1023) g_bsum[blockIdx.x] = s[1023];
}

__global__ void k_scan2(int nblocks) {
    __shared__ int s[256];
    int tid = threadIdx.x;
    int v = (tid < nblocks) ? g_bsum[tid] : 0;
    s[tid] = v;
    __syncthreads();
    for (int off = 1; off < 256; off <<= 1) {
        int t = 0;
        if (tid >= off) t = s[tid - off];
        __syncthreads();
        s[tid] += t;
        __syncthreads();
    }
    g_boff[tid] = s[tid] - v;   // exclusive
}

__global__ void k_scan3() {
    int i = blockIdx.x * blockDim.x + threadIdx.x;
    if (i < NTOT) {
        int val = g_inc[i] + g_boff[i >> 10];
        g_rowptr[i + 1] = val;
        g_wptr[i + 1] = val;
        if (i == 0) { g_rowptr[0] = 0; g_wptr[0] = 0; }
    }
}

__global__ void k_scatter(const int* __restrict__ rows,
                          const int* __restrict__ cols,
                          const float* __restrict__ vals) {
    int e = blockIdx.x * blockDim.x + threadIdx.x;
    if (e < NNZV) {
        int r = rows[e];
        int p = atomicAdd(&g_wptr[r], 1);
        g_edge[p] = make_int2(cols[e], __float_as_int(vals[e]));
    }
}

// ---------------- convert user+item fp32 -> fused fp16 buffer ----------------
__global__ void k_convert(const float2* __restrict__ user,
                          const float2* __restrict__ item) {
    int i = blockIdx.x * blockDim.x + threadIdx.x;   // over NTOT*32 float2-pairs
    if (i < NTOT * 32) {
        float2 v = (i < NUSER * 32) ? __ldcs(user + i)
                                    : __ldcs(item + (i - NUSER * 32));
        g_x0[i] = __floats2half2_rn(v.x, v.y);
    }
}

// ---------------- SpMM: 4 rows per warp, interleaved gather for MLP ----------
__global__ void k_spmm(const __half2* __restrict__ x,
                       __half2* __restrict__ y) {
    int lane = threadIdx.x & 31;
    int warp = threadIdx.x >> 5;
    int wid = blockIdx.x * 8 + warp;     // warp group index
    int row0 = wid * 4;

    int p[4], e[4];
    int maxlen = 0;
#pragma unroll
    for (int i = 0; i < 4; i++) {
        int r = row0 + i;
        if (r < NTOT) {
            p[i] = g_rowptr[r];
            e[i] = g_rowptr[r + 1];
        } else {
            p[i] = 0; e[i] = 0;
        }
        int len = e[i] - p[i];
        maxlen = max(maxlen, len);
    }

    float ax[4] = {0.f, 0.f, 0.f, 0.f};
    float ay[4] = {0.f, 0.f, 0.f, 0.f};

    for (int it = 0; it < maxlen; it++) {
#pragma unroll
        for (int i = 0; i < 4; i++) {
            int idx = p[i] + it;
            if (idx < e[i]) {
                int2 q = *reinterpret_cast<const int2*>(&g_edge[idx]); // uniform bcast
                float vv = __int_as_float(q.y);
                __half2 h = __ldg(x + (size_t)q.x * 32 + lane);
                float2 xv = __half22float2(h);
                ax[i] += vv * xv.x;
                ay[i] += vv * xv.y;
            }
        }
    }

#pragma unroll
    for (int i = 0; i < 4; i++) {
        int r = row0 + i;
        if (r < NTOT)
            y[(size_t)r * 32 + lane] = __floats2half2_rn(ax[i], ay[i]);
    }
}

// ---------------- epilogue: mean of 3 half bufs, GEMM 64x64, exp, views -------
// pair-per-lane layout: lane owns elements (2*lane, 2*lane+1)
__global__ void k_epilogue(const __half2* __restrict__ A,
                           const __half2* __restrict__ B,
                           const __half2* __restrict__ C,
                           const float* __restrict__ W,
                           const float* __restrict__ bias,
                           const float2* __restrict__ n1,
                           const float2* __restrict__ n2,
                           float2* __restrict__ out_mean,
                           float2* __restrict__ out_std,
                           float2* __restrict__ out_v1,
                           float2* __restrict__ out_v2) {
    __shared__ float2 Ws[64 * 32];   // Ws[d*32+l] = {W[d][2l], W[d][2l+1]}
    for (int i = threadIdx.x; i < 64 * 32; i += blockDim.x) {
        int d = i >> 5, l = i & 31;
        Ws[i] = *reinterpret_cast<const float2*>(W + d * 64 + 2 * l);
    }
    __syncthreads();

    int lane = threadIdx.x & 31;
    int warp = threadIdx.x >> 5;
    int rowbase = blockIdx.x * 64 + warp * 8;

    float2 b = __ldg(reinterpret_cast<const float2*>(bias) + lane);

    float m0[8], m1[8], ls0[8], ls1[8];
#pragma unroll
    for (int r = 0; r < 8; r++) {
        int row = rowbase + r;
        if (row >= NTOT) row = NTOT - 1;
        size_t ix = (size_t)row * 32 + lane;
        float2 a = __half22float2(__ldg(A + ix));
        float2 bb = __half22float2(__ldg(B + ix));
        float2 c = __half22float2(__ldg(C + ix));
        m0[r] = (a.x + bb.x + c.x) * (1.f / 3.f);
        m1[r] = (a.y + bb.y + c.y) * (1.f / 3.f);
        ls0[r] = b.x;
        ls1[r] = b.y;
    }

#pragma unroll 4
    for (int dd = 0; dd < 32; dd++) {
        float2 w0 = Ws[(2 * dd) * 32 + lane];       // W row 2dd
        float2 w1 = Ws[(2 * dd + 1) * 32 + lane];   // W row 2dd+1
#pragma unroll
        for (int r = 0; r < 8; r++) {
            float md0 = __shfl_sync(0xffffffffu, m0[r], dd);  // mean[2dd]
            float md1 = __shfl_sync(0xffffffffu, m1[r], dd);  // mean[2dd+1]
            ls0[r] += md0 * w0.x + md1 * w1.x;
            ls1[r] += md0 * w0.y + md1 * w1.y;
        }
    }

#pragma unroll
    for (int r = 0; r < 8; r++) {
        int row = rowbase + r;
        if (row < NTOT) {
            float s0 = __expf(ls0[r]);
            float s1 = __expf(ls1[r]);
            size_t ix = (size_t)row * 32 + lane;
            float2 na = __ldcs(n1 + ix);
            float2 nc = __ldcs(n2 + ix);
            __stcs(out_mean + ix, make_float2(m0[r], m1[r]));
            __stcs(out_std + ix,  make_float2(s0, s1));
            __stcs(out_v1 + ix, make_float2(m0[r] + s0 * na.x * VSCALE,
                                            m1[r] + s1 * na.y * VSCALE));
            __stcs(out_v2 + ix, make_float2(m0[r] + s0 * nc.x * VSCALE,
                                            m1[r] + s1 * nc.y * VSCALE));
        }
    }
}

// ---------------- launch ----------------
extern "C" void kernel_launch(void* const* d_in, const int* in_sizes, int n_in,
                              void* d_out, int out_size) {
    const float* user = (const float*)d_in[0];
    const float* item = (const float*)d_in[1];
    const float* W    = (const float*)d_in[2];
    const float* bias = (const float*)d_in[3];
    const int*   rows = (const int*)d_in[4];
    const int*   cols = (const int*)d_in[5];
    const float* vals = (const float*)d_in[6];
    const float* n1   = (const float*)d_in[7];
    const float* n2   = (const float*)d_in[8];

    __half2 *x0, *h1, *h2, *h3;
    cudaGetSymbolAddress((void**)&x0, g_x0);
    cudaGetSymbolAddress((void**)&h1, g_h1);
    cudaGetSymbolAddress((void**)&h2, g_h2);
    cudaGetSymbolAddress((void**)&h3, g_h3);

    float* out = (float*)d_out;
    float2* out_mean = (float2*)out;
    float2* out_std  = (float2*)(out + (size_t)NTOT * DD);
    float2* out_v1   = (float2*)(out + 2 * (size_t)NTOT * DD);
    float2* out_v2   = (float2*)(out + 3 * (size_t)NTOT * DD);

    const int T = 256;
    int nbN = (NTOT + T - 1) / T;
    int nbE = (NNZV + T - 1) / T;
    int nbScan = (NTOT + 1023) / 1024;
    int nbCvt = (NTOT * 32 + T - 1) / T;

    // sort COO -> CSR
    k_zero_cnt<<<nbN, T>>>();
    k_hist<<<nbE, T>>>(rows);
    k_scan1<<<nbScan, 1024>>>();
    k_scan2<<<1, 256>>>(nbScan);
    k_scan3<<<nbN, T>>>();
    k_scatter<<<nbE, T>>>(rows, cols, vals);

    // fp32 -> fp16 fused input
    k_convert<<<nbCvt, T>>>((const float2*)user, (const float2*)item);

    // 3 GCN layers: 4 rows per warp, 8 warps per block
    int nbSpmm = (NTOT / 4 + 7) / 8;    // 7032
    k_spmm<<<nbSpmm, T>>>(x0, h1);
    k_spmm<<<nbSpmm, T>>>(h1, h2);
    k_spmm<<<nbSpmm, T>>>(h2, h3);

    // epilogue: mean = (h1+h2+h3)/3, logstd GEMM, exp, views
    int nbEpi = (NTOT + 63) / 64;
    k_epilogue<<<nbEpi, T>>>(h1, h2, h3, W, bias,
                             (const float2*)n1, (const float2*)n2,
                             out_mean, out_std, out_v1, out_v2);
}

// round 5
// speedup vs baseline: 1.3799x; 1.0604x over previous
#include <cuda_runtime.h>
#include <cuda_fp16.h>

#define NUSER 150000
#define NITEM 75000
#define NTOT  225000
#define DD    64
#define NNZV  2000000
#define VSCALE 0.01f

// ---------------- static device scratch ----------------
__device__ int   g_cnt[NTOT];
__device__ int   g_inc[NTOT];
__device__ int   g_bsum[256];
__device__ int   g_boff[256];
__device__ int   g_rowptr[NTOT + 1];
__device__ int   g_wptr[NTOT + 1];
__device__ int2  g_edge[NNZV];                    // {col, val-as-int}
__device__ __half2 g_x0[(size_t)NTOT * 32];       // fused user+item, fp16
__device__ __half2 g_h1[(size_t)NTOT * 32];
__device__ __half2 g_h2[(size_t)NTOT * 32];

// ---------------- sort ----------------
__global__ void k_zero_cnt() {
    int i = blockIdx.x * blockDim.x + threadIdx.x;
    if (i < NTOT) g_cnt[i] = 0;
}

// fused: histogram (i < NNZV) + fp32->fp16 convert (i < NTOT*32)
__global__ void k_hist_convert(const int* __restrict__ rows,
                               const float2* __restrict__ user,
                               const float2* __restrict__ item) {
    int i = blockIdx.x * blockDim.x + threadIdx.x;
    if (i < NNZV) atomicAdd(&g_cnt[rows[i]], 1);
    if (i < NTOT * 32) {
        float2 v = (i < NUSER * 32) ? __ldcs(user + i)
                                    : __ldcs(item + (i - NUSER * 32));
        g_x0[i] = __floats2half2_rn(v.x, v.y);
    }
}

// shfl-based block scan, 1024 threads, 2 barriers
__global__ void k_scan1() {
    __shared__ int wsum[32];
    int tid = threadIdx.x;
    int lane = tid & 31;
    int wp = tid >> 5;
    int i = blockIdx.x * 1024 + tid;
    int v = (i < NTOT) ? g_cnt[i] : 0;
#pragma unroll
    for (int off = 1; off < 32; off <<= 1) {
        int t = __shfl_up_sync(0xffffffffu, v, off);
        if (lane >= off) v += t;
    }
    if (lane == 31) wsum[wp] = v;
    __syncthreads();
    if (wp == 0) {
        int s = wsum[lane];
#pragma unroll
        for (int off = 1; off < 32; off <<= 1) {
            int t = __shfl_up_sync(0xffffffffu, s, off);
            if (lane >= off) s += t;
        }
        wsum[lane] = s;
    }
    __syncthreads();
    if (wp > 0) v += wsum[wp - 1];
    if (i < NTOT) g_inc[i] = v;
    if (tid == 1023) g_bsum[blockIdx.x] = v;
}

__global__ void k_scan2(int nblocks) {
    int tid = threadIdx.x;
    int lane = tid & 31;
    int wp = tid >> 5;
    __shared__ int wsum[8];
    int v = (tid < nblocks) ? g_bsum[tid] : 0;
    int s = v;
#pragma unroll
    for (int off = 1; off < 32; off <<= 1) {
        int t = __shfl_up_sync(0xffffffffu, s, off);
        if (lane >= off) s += t;
    }
    if (lane == 31) wsum[wp] = s;
    __syncthreads();
    int add = 0;
#pragma unroll
    for (int w = 0; w < 8; w++)
        if (w < wp) add += wsum[w];
    g_boff[tid] = s + add - v;   // exclusive
}

__global__ void k_scan3() {
    int i = blockIdx.x * blockDim.x + threadIdx.x;
    if (i < NTOT) {
        int val = g_inc[i] + g_boff[i >> 10];
        g_rowptr[i + 1] = val;
        g_wptr[i + 1] = val;
        if (i == 0) { g_rowptr[0] = 0; g_wptr[0] = 0; }
    }
}

__global__ void k_scatter(const int* __restrict__ rows,
                          const int* __restrict__ cols,
                          const float* __restrict__ vals) {
    int e = blockIdx.x * blockDim.x + threadIdx.x;
    if (e < NNZV) {
        int r = rows[e];
        int p = atomicAdd(&g_wptr[r], 1);
        g_edge[p] = make_int2(cols[e], __float_as_int(vals[e]));
    }
}

// ---------------- SpMM layers 1-2: 4 rows per warp, interleaved ----------
__global__ void k_spmm(const __half2* __restrict__ x,
                       __half2* __restrict__ y) {
    int lane = threadIdx.x & 31;
    int warp = threadIdx.x >> 5;
    int wid = blockIdx.x * 8 + warp;
    int row0 = wid * 4;

    int p[4], e[4];
    int maxlen = 0;
#pragma unroll
    for (int i = 0; i < 4; i++) {
        int r = row0 + i;
        if (r < NTOT) { p[i] = g_rowptr[r]; e[i] = g_rowptr[r + 1]; }
        else          { p[i] = 0; e[i] = 0; }
        maxlen = max(maxlen, e[i] - p[i]);
    }

    float ax[4] = {0.f, 0.f, 0.f, 0.f};
    float ay[4] = {0.f, 0.f, 0.f, 0.f};

    for (int it = 0; it < maxlen; it++) {
#pragma unroll
        for (int i = 0; i < 4; i++) {
            int idx = p[i] + it;
            if (idx < e[i]) {
                int2 q = *reinterpret_cast<const int2*>(&g_edge[idx]);
                float vv = __int_as_float(q.y);
                float2 xv = __half22float2(__ldg(x + (size_t)q.x * 32 + lane));
                ax[i] += vv * xv.x;
                ay[i] += vv * xv.y;
            }
        }
    }

#pragma unroll
    for (int i = 0; i < 4; i++) {
        int r = row0 + i;
        if (r < NTOT)
            y[(size_t)r * 32 + lane] = __floats2half2_rn(ax[i], ay[i]);
    }
}

// ---------------- fused SpMM layer 3 + epilogue -----------------------------
// warp handles 4 rows: gathers y3 into registers, mean=(h1+h2+y3)/3,
// 64x64 GEMM via shfl, exp, views. lane owns features (2l, 2l+1).
__global__ void k_spmm3_epi(const __half2* __restrict__ h1,
                            const __half2* __restrict__ h2,
                            const float* __restrict__ W,
                            const float* __restrict__ bias,
                            const float2* __restrict__ n1,
                            const float2* __restrict__ n2,
                            float2* __restrict__ out_mean,
                            float2* __restrict__ out_std,
                            float2* __restrict__ out_v1,
                            float2* __restrict__ out_v2) {
    __shared__ float2 Ws[64 * 32];   // Ws[d*32+l] = {W[d][2l], W[d][2l+1]}
    for (int i = threadIdx.x; i < 64 * 32; i += blockDim.x) {
        int d = i >> 5, l = i & 31;
        Ws[i] = *reinterpret_cast<const float2*>(W + d * 64 + 2 * l);
    }
    __syncthreads();

    int lane = threadIdx.x & 31;
    int warp = threadIdx.x >> 5;
    int wid = blockIdx.x * 8 + warp;
    int row0 = wid * 4;

    // ---- SpMM layer 3 (gather from h2) ----
    int p[4], e[4];
    int maxlen = 0;
#pragma unroll
    for (int i = 0; i < 4; i++) {
        int r = row0 + i;
        if (r < NTOT) { p[i] = g_rowptr[r]; e[i] = g_rowptr[r + 1]; }
        else          { p[i] = 0; e[i] = 0; }
        maxlen = max(maxlen, e[i] - p[i]);
    }

    float ax[4] = {0.f, 0.f, 0.f, 0.f};
    float ay[4] = {0.f, 0.f, 0.f, 0.f};
    for (int it = 0; it < maxlen; it++) {
#pragma unroll
        for (int i = 0; i < 4; i++) {
            int idx = p[i] + it;
            if (idx < e[i]) {
                int2 q = *reinterpret_cast<const int2*>(&g_edge[idx]);
                float vv = __int_as_float(q.y);
                float2 xv = __half22float2(__ldg(h2 + (size_t)q.x * 32 + lane));
                ax[i] += vv * xv.x;
                ay[i] += vv * xv.y;
            }
        }
    }

    // ---- mean + GEMM + views ----
    float2 b = __ldg(reinterpret_cast<const float2*>(bias) + lane);

    float m0[4], m1[4], ls0[4], ls1[4];
#pragma unroll
    for (int r = 0; r < 4; r++) {
        int row = row0 + r;
        int rc = (row < NTOT) ? row : (NTOT - 1);
        size_t ix = (size_t)rc * 32 + lane;
        float2 a1 = __half22float2(__ldg(h1 + ix));
        float2 a2 = __half22float2(__ldg(h2 + ix));
        m0[r] = (a1.x + a2.x + ax[r]) * (1.f / 3.f);
        m1[r] = (a1.y + a2.y + ay[r]) * (1.f / 3.f);
        ls0[r] = b.x;
        ls1[r] = b.y;
    }

#pragma unroll 4
    for (int dd = 0; dd < 32; dd++) {
        float2 w0 = Ws[(2 * dd) * 32 + lane];
        float2 w1 = Ws[(2 * dd + 1) * 32 + lane];
#pragma unroll
        for (int r = 0; r < 4; r++) {
            float md0 = __shfl_sync(0xffffffffu, m0[r], dd);
            float md1 = __shfl_sync(0xffffffffu, m1[r], dd);
            ls0[r] += md0 * w0.x + md1 * w1.x;
            ls1[r] += md0 * w0.y + md1 * w1.y;
        }
    }

#pragma unroll
    for (int r = 0; r < 4; r++) {
        int row = row0 + r;
        if (row < NTOT) {
            float s0 = __expf(ls0[r]);
            float s1 = __expf(ls1[r]);
            size_t ix = (size_t)row * 32 + lane;
            float2 na = __ldcs(n1 + ix);
            float2 nc = __ldcs(n2 + ix);
            __stcs(out_mean + ix, make_float2(m0[r], m1[r]));
            __stcs(out_std + ix,  make_float2(s0, s1));
            __stcs(out_v1 + ix, make_float2(m0[r] + s0 * na.x * VSCALE,
                                            m1[r] + s1 * na.y * VSCALE));
            __stcs(out_v2 + ix, make_float2(m0[r] + s0 * nc.x * VSCALE,
                                            m1[r] + s1 * nc.y * VSCALE));
        }
    }
}

// ---------------- launch ----------------
extern "C" void kernel_launch(void* const* d_in, const int* in_sizes, int n_in,
                              void* d_out, int out_size) {
    const float* user = (const float*)d_in[0];
    const float* item = (const float*)d_in[1];
    const float* W    = (const float*)d_in[2];
    const float* bias = (const float*)d_in[3];
    const int*   rows = (const int*)d_in[4];
    const int*   cols = (const int*)d_in[5];
    const float* vals = (const float*)d_in[6];
    const float* n1   = (const float*)d_in[7];
    const float* n2   = (const float*)d_in[8];

    __half2 *x0, *h1, *h2;
    cudaGetSymbolAddress((void**)&x0, g_x0);
    cudaGetSymbolAddress((void**)&h1, g_h1);
    cudaGetSymbolAddress((void**)&h2, g_h2);

    float* out = (float*)d_out;
    float2* out_mean = (float2*)out;
    float2* out_std  = (float2*)(out + (size_t)NTOT * DD);
    float2* out_v1   = (float2*)(out + 2 * (size_t)NTOT * DD);
    float2* out_v2   = (float2*)(out + 3 * (size_t)NTOT * DD);

    const int T = 256;
    int nbN = (NTOT + T - 1) / T;
    int nbScan = (NTOT + 1023) / 1024;
    int nbHC = (NTOT * 32 + T - 1) / T;   // covers both NNZV and NTOT*32
    int nbE = (NNZV + T - 1) / T;

    // sort COO -> CSR (+ fused fp16 convert)
    k_zero_cnt<<<nbN, T>>>();
    k_hist_convert<<<nbHC, T>>>(rows, (const float2*)user, (const float2*)item);
    k_scan1<<<nbScan, 1024>>>();
    k_scan2<<<1, 256>>>(nbScan);
    k_scan3<<<nbN, T>>>();
    k_scatter<<<nbE, T>>>(rows, cols, vals);

    // GCN layers 1-2
    int nbSpmm = (NTOT / 4 + 7) / 8;    // 7032
    k_spmm<<<nbSpmm, T>>>(x0, h1);
    k_spmm<<<nbSpmm, T>>>(h1, h2);

    // layer 3 fused with epilogue
    k_spmm3_epi<<<nbSpmm, T>>>(h1, h2, W, bias,
                               (const float2*)n1, (const float2*)n2,
                               out_mean, out_std, out_v1, out_v2);
}

// round 6
// speedup vs baseline: 1.4813x; 1.0735x over previous
#include <cuda_runtime.h>
#include <cuda_fp16.h>

#define NUSER 150000
#define NITEM 75000
#define NTOT  225000
#define DD    64
#define NNZV  2000000
#define VSCALE 0.01f

// ---------------- static device scratch ----------------
__device__ int   g_cnt[NTOT];
__device__ int   g_inc[NTOT];
__device__ int   g_bsum[256];
__device__ int   g_rowptr[NTOT + 1];
__device__ int   g_wptr[NTOT + 1];
__device__ int2  g_edge[NNZV];                    // {col, val-as-int}
__device__ __half2 g_x0[(size_t)NTOT * 32];       // fused user+item, fp16
__device__ __half2 g_h1[(size_t)NTOT * 32];
__device__ __half2 g_h2[(size_t)NTOT * 32];

// ---------------- histogram ----------------
__global__ void k_hist(const int* __restrict__ rows) {
    int e = blockIdx.x * blockDim.x + threadIdx.x;
    if (e < NNZV) atomicAdd(&g_cnt[__ldcs(rows + e)], 1);
}

// shfl-based block scan, 1024 threads, 2 barriers
__global__ void k_scan1() {
    __shared__ int wsum[32];
    int tid = threadIdx.x;
    int lane = tid & 31;
    int wp = tid >> 5;
    int i = blockIdx.x * 1024 + tid;
    int v = (i < NTOT) ? g_cnt[i] : 0;
#pragma unroll
    for (int off = 1; off < 32; off <<= 1) {
        int t = __shfl_up_sync(0xffffffffu, v, off);
        if (lane >= off) v += t;
    }
    if (lane == 31) wsum[wp] = v;
    __syncthreads();
    if (wp == 0) {
        int s = wsum[lane];
#pragma unroll
        for (int off = 1; off < 32; off <<= 1) {
            int t = __shfl_up_sync(0xffffffffu, s, off);
            if (lane >= off) s += t;
        }
        wsum[lane] = s;
    }
    __syncthreads();
    if (wp > 0) v += wsum[wp - 1];
    if (i < NTOT) g_inc[i] = v;
    if (tid == 1023) g_bsum[blockIdx.x] = v;
}

// merged scan2+scan3: each block (256 thr) shares one 1024-bucket; warp 0
// computes the exclusive prefix of g_bsum over [0, bucket) itself.
__global__ void k_scan23(int nbScan) {
    __shared__ int s_off;
    int tid = threadIdx.x;
    int i = blockIdx.x * 256 + tid;
    int bucket = (blockIdx.x * 256) >> 10;     // same for whole block
    if (tid < 32) {
        int acc = 0;
        for (int j = tid; j < bucket; j += 32) acc += g_bsum[j];
#pragma unroll
        for (int off = 16; off > 0; off >>= 1)
            acc += __shfl_down_sync(0xffffffffu, acc, off);
        if (tid == 0) s_off = acc;
    }
    __syncthreads();
    if (i < NTOT) {
        int val = g_inc[i] + s_off;
        g_rowptr[i + 1] = val;
        g_wptr[i + 1] = val;
        if (i == 0) { g_rowptr[0] = 0; g_wptr[0] = 0; }
    }
}

// fused: scatter (first nbE blocks) + fp32->fp16 convert (remaining blocks)
__global__ void k_scatter_convert(const int* __restrict__ rows,
                                  const int* __restrict__ cols,
                                  const float* __restrict__ vals,
                                  const float2* __restrict__ user,
                                  const float2* __restrict__ item,
                                  int nbE) {
    if (blockIdx.x < nbE) {
        int e = blockIdx.x * blockDim.x + threadIdx.x;
        if (e < NNZV) {
            int r = __ldcs(rows + e);
            int p = atomicAdd(&g_wptr[r], 1);
            g_edge[p] = make_int2(__ldcs(cols + e),
                                  __float_as_int(__ldcs(vals + e)));
        }
    } else {
        int base = (blockIdx.x - nbE) * blockDim.x * 4 + threadIdx.x;
#pragma unroll
        for (int u = 0; u < 4; u++) {
            int i = base + u * blockDim.x;
            if (i < NTOT * 32) {
                float2 v = (i < NUSER * 32) ? __ldcs(user + i)
                                            : __ldcs(item + (i - NUSER * 32));
                g_x0[i] = __floats2half2_rn(v.x, v.y);
            }
        }
    }
}

// ---------------- SpMM layers 1-2: 4 rows per warp, interleaved ----------
__global__ void k_spmm(const __half2* __restrict__ x,
                       __half2* __restrict__ y) {
    int lane = threadIdx.x & 31;
    int warp = threadIdx.x >> 5;
    int wid = blockIdx.x * 8 + warp;
    int row0 = wid * 4;
    if (row0 >= NTOT) return;

    int4 rp = *reinterpret_cast<const int4*>(&g_rowptr[row0]);
    int r4 = g_rowptr[row0 + 4];
    int p[4] = {rp.x, rp.y, rp.z, rp.w};
    int e[4] = {rp.y, rp.z, rp.w, r4};
    int maxlen = max(max(e[0] - p[0], e[1] - p[1]),
                     max(e[2] - p[2], e[3] - p[3]));

    float ax[4] = {0.f, 0.f, 0.f, 0.f};
    float ay[4] = {0.f, 0.f, 0.f, 0.f};

    for (int it = 0; it < maxlen; it++) {
#pragma unroll
        for (int i = 0; i < 4; i++) {
            int idx = p[i] + it;
            if (idx < e[i]) {
                int2 q = *reinterpret_cast<const int2*>(&g_edge[idx]);
                float vv = __int_as_float(q.y);
                float2 xv = __half22float2(__ldg(x + (size_t)q.x * 32 + lane));
                ax[i] += vv * xv.x;
                ay[i] += vv * xv.y;
            }
        }
    }

#pragma unroll
    for (int i = 0; i < 4; i++)
        y[(size_t)(row0 + i) * 32 + lane] = __floats2half2_rn(ax[i], ay[i]);
}

// ---------------- fused SpMM layer 3 + epilogue -----------------------------
__global__ void k_spmm3_epi(const __half2* __restrict__ h1,
                            const __half2* __restrict__ h2,
                            const float* __restrict__ W,
                            const float* __restrict__ bias,
                            const float2* __restrict__ n1,
                            const float2* __restrict__ n2,
                            float2* __restrict__ out_mean,
                            float2* __restrict__ out_std,
                            float2* __restrict__ out_v1,
                            float2* __restrict__ out_v2) {
    __shared__ float2 Ws[64 * 32];   // Ws[d*32+l] = {W[d][2l], W[d][2l+1]}
    for (int i = threadIdx.x; i < 64 * 32; i += blockDim.x) {
        int d = i >> 5, l = i & 31;
        Ws[i] = *reinterpret_cast<const float2*>(W + d * 64 + 2 * l);
    }
    __syncthreads();

    int lane = threadIdx.x & 31;
    int warp = threadIdx.x >> 5;
    int wid = blockIdx.x * 8 + warp;
    int row0 = wid * 4;
    if (row0 >= NTOT) return;

    int4 rp = *reinterpret_cast<const int4*>(&g_rowptr[row0]);
    int r4 = g_rowptr[row0 + 4];
    int p[4] = {rp.x, rp.y, rp.z, rp.w};
    int e[4] = {rp.y, rp.z, rp.w, r4};
    int maxlen = max(max(e[0] - p[0], e[1] - p[1]),
                     max(e[2] - p[2], e[3] - p[3]));

    float ax[4] = {0.f, 0.f, 0.f, 0.f};
    float ay[4] = {0.f, 0.f, 0.f, 0.f};
    for (int it = 0; it < maxlen; it++) {
#pragma unroll
        for (int i = 0; i < 4; i++) {
            int idx = p[i] + it;
            if (idx < e[i]) {
                int2 q = *reinterpret_cast<const int2*>(&g_edge[idx]);
                float vv = __int_as_float(q.y);
                float2 xv = __half22float2(__ldg(h2 + (size_t)q.x * 32 + lane));
                ax[i] += vv * xv.x;
                ay[i] += vv * xv.y;
            }
        }
    }

    // ---- mean + GEMM + views ----
    float2 b = __ldg(reinterpret_cast<const float2*>(bias) + lane);

    float m0[4], m1[4], ls0[4], ls1[4];
#pragma unroll
    for (int r = 0; r < 4; r++) {
        size_t ix = (size_t)(row0 + r) * 32 + lane;
        float2 a1 = __half22float2(__ldg(h1 + ix));
        float2 a2 = __half22float2(__ldg(h2 + ix));
        m0[r] = (a1.x + a2.x + ax[r]) * (1.f / 3.f);
        m1[r] = (a1.y + a2.y + ay[r]) * (1.f / 3.f);
        ls0[r] = b.x;
        ls1[r] = b.y;
    }

#pragma unroll 4
    for (int dd = 0; dd < 32; dd++) {
        float2 w0 = Ws[(2 * dd) * 32 + lane];
        float2 w1 = Ws[(2 * dd + 1) * 32 + lane];
#pragma unroll
        for (int r = 0; r < 4; r++) {
            float md0 = __shfl_sync(0xffffffffu, m0[r], dd);
            float md1 = __shfl_sync(0xffffffffu, m1[r], dd);
            ls0[r] += md0 * w0.x + md1 * w1.x;
            ls1[r] += md0 * w0.y + md1 * w1.y;
        }
    }

#pragma unroll
    for (int r = 0; r < 4; r++) {
        float s0 = __expf(ls0[r]);
        float s1 = __expf(ls1[r]);
        size_t ix = (size_t)(row0 + r) * 32 + lane;
        float2 na = __ldcs(n1 + ix);
        float2 nc = __ldcs(n2 + ix);
        __stcs(out_mean + ix, make_float2(m0[r], m1[r]));
        __stcs(out_std + ix,  make_float2(s0, s1));
        __stcs(out_v1 + ix, make_float2(m0[r] + s0 * na.x * VSCALE,
                                        m1[r] + s1 * na.y * VSCALE));
        __stcs(out_v2 + ix, make_float2(m0[r] + s0 * nc.x * VSCALE,
                                        m1[r] + s1 * nc.y * VSCALE));
    }
}

// ---------------- launch ----------------
extern "C" void kernel_launch(void* const* d_in, const int* in_sizes, int n_in,
                              void* d_out, int out_size) {
    const float* user = (const float*)d_in[0];
    const float* item = (const float*)d_in[1];
    const float* W    = (const float*)d_in[2];
    const float* bias = (const float*)d_in[3];
    const int*   rows = (const int*)d_in[4];
    const int*   cols = (const int*)d_in[5];
    const float* vals = (const float*)d_in[6];
    const float* n1   = (const float*)d_in[7];
    const float* n2   = (const float*)d_in[8];

    __half2 *x0, *h1, *h2;
    cudaGetSymbolAddress((void**)&x0, g_x0);
    cudaGetSymbolAddress((void**)&h1, g_h1);
    cudaGetSymbolAddress((void**)&h2, g_h2);
    void* cntp;
    cudaGetSymbolAddress(&cntp, g_cnt);

    float* out = (float*)d_out;
    float2* out_mean = (float2*)out;
    float2* out_std  = (float2*)(out + (size_t)NTOT * DD);
    float2* out_v1   = (float2*)(out + 2 * (size_t)NTOT * DD);
    float2* out_v2   = (float2*)(out + 3 * (size_t)NTOT * DD);

    const int T = 256;
    int nbScan = (NTOT + 1023) / 1024;          // 220
    int nbS23 = (NTOT + 255) / 256;             // 879
    int nbE = (NNZV + T - 1) / T;               // 7813
    int nbCvt = (NTOT * 32 + T * 4 - 1) / (T * 4);  // 7032

    // sort COO -> CSR, convert fused into scatter launch
    cudaMemsetAsync(cntp, 0, NTOT * sizeof(int));
    k_hist<<<nbE, T>>>(rows);
    k_scan1<<<nbScan, 1024>>>();
    k_scan23<<<nbS23, T>>>(nbScan);
    k_scatter_convert<<<nbE + nbCvt, T>>>(rows, cols, vals,
                                          (const float2*)user,
                                          (const float2*)item, nbE);

    // GCN layers 1-2
    int nbSpmm = (NTOT / 4 + 7) / 8;    // 7032
    k_spmm<<<nbSpmm, T>>>(x0, h1);
    k_spmm<<<nbSpmm, T>>>(h1, h2);

    // layer 3 fused with epilogue
    k_spmm3_epi<<<nbSpmm, T>>>(h1, h2, W, bias,
                               (const float2*)n1, (const float2*)n2,
                               out_mean, out_std, out_v1, out_v2);
}